// round 11
// baseline (speedup 1.0000x reference)
#include <cuda_runtime.h>
#include <cuda_bf16.h>

#define BB 4
#define TT 512
#define VV 8000
#define HH 7
#define VP 8192          // padded vocab stride
#define DMAX_TH 250.0f   // |1/r| threshold  <=>  |r| < 4e-3
#define GUARD_TH 4e-3f

// Scratch (allocation-free rule: __device__ globals)
__device__ float g_vocab[3][HH][VP];   // [0]=angle, [1]=sqrt2*A/h^d*sin, [2]=sqrt2*A/h^d*cos
__device__ float g_C[BB * TT * VV];    // 65.5 MB
__device__ int   g_pad_sink;

// ---- f32x2 packed helpers (ptxas aliases mov.b64 pack/unpack to nothing) ----
__device__ __forceinline__ unsigned long long pk2(float lo, float hi) {
    unsigned long long r;
    asm("mov.b64 %0, {%1, %2};" : "=l"(r) : "f"(lo), "f"(hi));
    return r;
}
__device__ __forceinline__ void upk2(unsigned long long p, float& lo, float& hi) {
    asm("mov.b64 {%0, %1}, %2;" : "=f"(lo), "=f"(hi) : "l"(p));
}
__device__ __forceinline__ unsigned long long fma2(unsigned long long a,
                                                   unsigned long long b,
                                                   unsigned long long c) {
    unsigned long long d;
    asm("fma.rn.f32x2 %0, %1, %2, %3;" : "=l"(d) : "l"(a), "l"(b), "l"(c));
    return d;
}
__device__ __forceinline__ unsigned long long add2(unsigned long long a,
                                                   unsigned long long b) {
    unsigned long long d;
    asm("add.rn.f32x2 %0, %1, %2;" : "=l"(d) : "l"(a), "l"(b));
    return d;
}
__device__ __forceinline__ float frcp(float x) {
    float d;
    asm("rcp.approx.f32 %0, %1;" : "=f"(d) : "f"(x));
    return d;
}

// ---------------------------------------------------------------------------
// Kernel A: per-vocab harmonic tables; sqrt(2) baked into both trig entries
// so any product of two entries carries the final 2.0 factor.
// ---------------------------------------------------------------------------
__global__ void build_tables(const float* __restrict__ freq,
                             const float* __restrict__ amp,
                             const float* __restrict__ decay) {
    int v = blockIdx.x * blockDim.x + threadIdx.x;
    if (v >= VV) return;
    float f   = freq[v];
    float A   = amp[v];
    float dec = decay[0];
    const float TWO_PI = 6.2831853071795864769f;
    const float SQRT2  = 1.4142135623730951f;
#pragma unroll
    for (int j = 0; j < HH; j++) {
        float h   = (float)(j + 1);
        float ang = TWO_PI * f * h;
        float Ah  = SQRT2 * A / powf(h, dec);
        float s, c;
        sincosf(ang, &s, &c);
        g_vocab[0][j][v] = ang;
        g_vocab[1][j][v] = Ah * s;
        g_vocab[2][j][v] = Ah * c;
    }
}

// ---------------------------------------------------------------------------
// Kernel B: packed-f32x2 fast body. Per i: token broadcast pairs via LDS.64
// from duplicated smem; 3 packed j-pairs + 1 scalar j. Collision detection via
// max|d| (reuses RCP result; rcp(0)=inf triggers). Rare scalar recompute.
// ---------------------------------------------------------------------------
__global__ void __launch_bounds__(256) wave_C(const int* __restrict__ ids) {
    __shared__ float sA[16][HH][2];   // duplicated halves -> broadcast LDS.64
    __shared__ float sS[16][HH][2];
    __shared__ float sC[16][HH][2];
    __shared__ int   sid[16];

    const int b   = blockIdx.z;
    const int t0  = blockIdx.y * 16;
    const int tid = threadIdx.x;

    if (tid < 16) sid[tid] = ids[b * TT + t0 + tid];
    __syncthreads();
    if (tid < 16 * HH) {                 // 112 (tt,i) pairs
        int ttl = tid / HH, i = tid % HH;
        int u   = sid[ttl];
        float a = g_vocab[0][i][u];
        float s = g_vocab[1][i][u];
        float c = g_vocab[2][i][u];
        sA[ttl][i][0] = a; sA[ttl][i][1] = a;
        sS[ttl][i][0] = s; sS[ttl][i][1] = s;
        sC[ttl][i][0] = c; sC[ttl][i][1] = c;
    }
    __syncthreads();

    const int v  = blockIdx.x * 256 + tid;
    const int vc = (v < VV) ? v : (VV - 1);
    const bool ok = (v < VV);

    // Vocab-side packed pairs for j={0,1},{2,3},{4,5}; scalars for j=6.
    unsigned long long nvb2[3], vcs2[3], nvs2[3];
#pragma unroll
    for (int jp = 0; jp < 3; jp++) {
        int j0 = 2 * jp, j1 = 2 * jp + 1;
        nvb2[jp] = pk2(-g_vocab[0][j0][vc], -g_vocab[0][j1][vc]);
        vcs2[jp] = pk2( g_vocab[2][j0][vc],  g_vocab[2][j1][vc]);
        nvs2[jp] = pk2(-g_vocab[1][j0][vc], -g_vocab[1][j1][vc]);
    }
    const float nvb6 = -g_vocab[0][6][vc];
    const float vcs6 =  g_vocab[2][6][vc];
    const float nvs6 = -g_vocab[1][6][vc];

#pragma unroll 1                         // keep both bodies in I$ once
    for (int ttl = 0; ttl < 16; ttl++) {
        unsigned long long acc2 = pk2(0.0f, 0.0f);
        float accs = 0.0f;
        float dmax = 0.0f;
#pragma unroll
        for (int i = 0; i < HH; i++) {
            unsigned long long a2  = *(const unsigned long long*)sA[ttl][i];
            unsigned long long sa2 = *(const unsigned long long*)sS[ttl][i];
            unsigned long long ca2 = *(const unsigned long long*)sC[ttl][i];
            unsigned long long S1 = pk2(0.0f, 0.0f);
            unsigned long long S2 = pk2(0.0f, 0.0f);
#pragma unroll
            for (int jp = 0; jp < 3; jp++) {
                unsigned long long r2 = add2(a2, nvb2[jp]);
                float r0, r1; upk2(r2, r0, r1);
                float d0 = frcp(r0), d1 = frcp(r1);
                dmax = fmaxf(dmax, fabsf(d0));
                dmax = fmaxf(dmax, fabsf(d1));
                unsigned long long d2 = pk2(d0, d1);
                S1 = fma2(vcs2[jp], d2, S1);
                S2 = fma2(nvs2[jp], d2, S2);
            }
            // scalar j = 6 (lo half of broadcast pairs aliases the scalar)
            float a, au, sa, sau, ca, cau;
            upk2(a2, a, au); upk2(sa2, sa, sau); upk2(ca2, ca, cau);
            {
                float r = a + nvb6;
                float d = frcp(r);
                dmax = fmaxf(dmax, fabsf(d));
                accs = fmaf(sa, vcs6 * d, accs);
                accs = fmaf(ca, nvs6 * d, accs);
            }
            acc2 = fma2(sa2, S1, acc2);
            acc2 = fma2(ca2, S2, acc2);
        }
        float aLo, aHi; upk2(acc2, aLo, aHi);
        float accT = aLo + aHi + accs;

        if (dmax > DMAX_TH) {
            // Rare guarded recompute (R1-validated scalar math, sqrt2-scaled tables).
            float vbv[HH], vsv[HH], vcv[HH];
#pragma unroll
            for (int jp = 0; jp < 3; jp++) {
                float x0, x1;
                upk2(nvb2[jp], x0, x1); vbv[2*jp] = -x0; vbv[2*jp+1] = -x1;
                upk2(nvs2[jp], x0, x1); vsv[2*jp] = -x0; vsv[2*jp+1] = -x1;
                upk2(vcs2[jp], x0, x1); vcv[2*jp] =  x0; vcv[2*jp+1] =  x1;
            }
            vbv[6] = -nvb6; vsv[6] = -nvs6; vcv[6] = vcs6;
            accT = 0.0f;
#pragma unroll
            for (int i = 0; i < HH; i++) {
                float a = sA[ttl][i][0];
                float s = sS[ttl][i][0];
                float c = sC[ttl][i][0];
#pragma unroll
                for (int j = 0; j < HH; j++) {
                    float r   = a - vbv[j];
                    float d   = frcp(r);
                    float num = fmaf(s, vcv[j], -(c * vsv[j]));  // 2AA*sin(r)
                    float val = num * d;
                    float alt = fmaf(s, vsv[j], c * vcv[j]);     // 2AA*cos(r) ~ limit
                    accT += (fabsf(r) < GUARD_TH) ? alt : val;
                }
            }
        }
        if (ok) g_C[(size_t)((b * TT + t0 + ttl)) * VV + v] = accT;
    }
}

// ---------------------------------------------------------------------------
// Kernel C: exclusive cumsum over t per (b,v) column; 8-wide load batching
// ---------------------------------------------------------------------------
__global__ void __launch_bounds__(256) cumshift(float* __restrict__ out) {
    int idx = blockIdx.x * blockDim.x + threadIdx.x;
    if (idx >= BB * VV) return;
    int b = idx / VV;
    int v = idx - b * VV;
    const float* crow = g_C + (size_t)b * TT * VV + v;
    float*       orow = out + (size_t)b * TT * VV + v;
    float run = 0.0f;
#pragma unroll 1
    for (int t = 0; t < TT; t += 8) {
        float x[8];
#pragma unroll
        for (int k = 0; k < 8; k++) x[k] = crow[(size_t)(t + k) * VV];
#pragma unroll
        for (int k = 0; k < 8; k++) { orow[(size_t)(t + k) * VV] = run; run += x[k]; }
    }
}

// Pad kernel: launch cycle length 4 so ncu (-s 5 -c 1) lands on wave_C.
__global__ void pad_k() { if (threadIdx.x == 0) g_pad_sink = 1; }

// ---------------------------------------------------------------------------
extern "C" void kernel_launch(void* const* d_in, const int* in_sizes, int n_in,
                              void* d_out, int out_size) {
    const int*   ids   = (const int*)d_in[0];
    const float* freq  = (const float*)d_in[1];
    const float* amp   = (const float*)d_in[2];
    const float* decay = (const float*)d_in[3];
    // d_in[4] = chunk_size: result independent of chunking; ignored.

    build_tables<<<(VV + 255) / 256, 256>>>(freq, amp, decay);

    dim3 gridB((VV + 255) / 256, TT / 16, BB);
    wave_C<<<gridB, 256>>>(ids);

    cumshift<<<(BB * VV + 255) / 256, 256>>>((float*)d_out);

    pad_k<<<1, 32>>>();
}

// round 12
// speedup vs baseline: 1.0685x; 1.0685x over previous
#include <cuda_runtime.h>
#include <cuda_bf16.h>

#define BB 4
#define TT 512
#define VV 8000
#define HH 7
#define VP 8192          // padded vocab stride
#define GUARD_TH 4e-3f

// Scratch (allocation-free rule: __device__ globals)
__device__ float g_vocab[3][HH][VP];   // [0]=angle, [1]=sqrt2*A/h^d*sin, [2]=sqrt2*A/h^d*cos
__device__ float g_C[BB * TT * VV];    // 65.5 MB

__device__ __forceinline__ float frcp(float x) {
    float d;
    asm("rcp.approx.f32 %0, %1;" : "=f"(d) : "f"(x));
    return d;
}

// ---------------------------------------------------------------------------
// Kernel A: per-vocab harmonic tables; sqrt(2) baked into both trig entries
// so any product of two trig entries carries the final 2.0 factor.
// ---------------------------------------------------------------------------
__global__ void build_tables(const float* __restrict__ freq,
                             const float* __restrict__ amp,
                             const float* __restrict__ decay) {
    int v = blockIdx.x * blockDim.x + threadIdx.x;
    if (v >= VV) return;
    float f   = freq[v];
    float A   = amp[v];
    float dec = decay[0];
    const float TWO_PI = 6.2831853071795864769f;
    const float SQRT2  = 1.4142135623730951f;
#pragma unroll
    for (int j = 0; j < HH; j++) {
        float h   = (float)(j + 1);
        float ang = TWO_PI * f * h;
        float Ah  = SQRT2 * A / powf(h, dec);
        float s, c;
        sincosf(ang, &s, &c);
        g_vocab[0][j][v] = ang;
        g_vocab[1][j][v] = Ah * s;
        g_vocab[2][j][v] = Ah * c;
    }
}

// ---------------------------------------------------------------------------
// Kernel B: batch-2 reciprocal form.
//   For j-pair (j0,j1):  vcs0/r0 + vcs1/r1 = num1 * inv,  inv = 1/(r0*r1)
//   num1 = fma(a, vcs0+vcs1, -(vcs0*b1 + vcs1*b0))   (1 FMA, precision-safe)
//   r0,r1 by exact FADD -> p=r0*r1 single rounding; rmin guard (theta=4e-3)
//   -> 1 MUFU per 2 terms (was 1 per term). Rare exact recompute per ttl.
// ---------------------------------------------------------------------------
__global__ void __launch_bounds__(256) wave_C(const int* __restrict__ ids, int b) {
    __shared__ float sA[16][HH];
    __shared__ float sS[16][HH];
    __shared__ float sC[16][HH];
    __shared__ int   sid[16];

    const int t0  = blockIdx.y * 16;
    const int tid = threadIdx.x;

    if (tid < 16) sid[tid] = ids[b * TT + t0 + tid];
    __syncthreads();
    if (tid < 16 * HH) {                 // 112 (tt,i) pairs
        int ttl = tid / HH, i = tid % HH;
        int u   = sid[ttl];
        sA[ttl][i] = g_vocab[0][i][u];
        sS[ttl][i] = g_vocab[1][i][u];
        sC[ttl][i] = g_vocab[2][i][u];
    }
    __syncthreads();

    const int v  = blockIdx.x * 256 + tid;
    const int vc = (v < VV) ? v : (VV - 1);
    const bool ok = (v < VV);

    // Per-v pair constants: jp pairs (0,1),(2,3),(4,5); scalar j=6.
    float nb0[3], nb1[3], cS1[3], cM1[3], cS2[3], cM2[3];
#pragma unroll
    for (int jp = 0; jp < 3; jp++) {
        int j0 = 2 * jp, j1 = 2 * jp + 1;
        float b0 = g_vocab[0][j0][vc], b1 = g_vocab[0][j1][vc];
        float c0 = g_vocab[2][j0][vc], c1 = g_vocab[2][j1][vc];
        float s0 = g_vocab[1][j0][vc], s1 = g_vocab[1][j1][vc];
        nb0[jp] = -b0;
        nb1[jp] = -b1;
        cS1[jp] = c0 + c1;                       // S1 (cos side)
        cM1[jp] = -fmaf(c0, b1, c1 * b0);
        cS2[jp] = -(s0 + s1);                    // S2 (neg-sin side)
        cM2[jp] = fmaf(s0, b1, s1 * b0);
    }
    const float nb6  = -g_vocab[0][6][vc];
    const float vcs6 =  g_vocab[2][6][vc];
    const float nvs6 = -g_vocab[1][6][vc];

#pragma unroll 1                         // keep bodies in I$ once
    for (int ttl = 0; ttl < 16; ttl++) {
        float acc  = 0.0f;
        float rmin = 1e30f;
#pragma unroll
        for (int i = 0; i < HH; i++) {
            const float a  = sA[ttl][i];
            const float sa = sS[ttl][i];
            const float ca = sC[ttl][i];
            float S1 = 0.0f, S2 = 0.0f;
#pragma unroll
            for (int jp = 0; jp < 3; jp++) {
                float r0 = a + nb0[jp];
                float r1 = a + nb1[jp];
                rmin = fminf(rmin, fabsf(r0));
                rmin = fminf(rmin, fabsf(r1));
                float p   = r0 * r1;
                float inv = frcp(p);
                float n1  = fmaf(a, cS1[jp], cM1[jp]);
                float n2  = fmaf(a, cS2[jp], cM2[jp]);
                S1 = fmaf(n1, inv, S1);
                S2 = fmaf(n2, inv, S2);
            }
            {   // scalar j = 6
                float r = a + nb6;
                rmin = fminf(rmin, fabsf(r));
                float d = frcp(r);
                S1 = fmaf(vcs6, d, S1);
                S2 = fmaf(nvs6, d, S2);
            }
            acc = fmaf(sa, S1, acc);
            acc = fmaf(ca, S2, acc);
        }
        if (rmin < GUARD_TH) {
            // Rare exact recompute (R1-validated math; cold LDG reloads).
            acc = 0.0f;
#pragma unroll 1
            for (int i = 0; i < HH; i++) {
                float a  = sA[ttl][i];
                float sa = sS[ttl][i];
                float ca = sC[ttl][i];
#pragma unroll
                for (int j = 0; j < HH; j++) {
                    float bj  = g_vocab[0][j][vc];
                    float vsj = g_vocab[1][j][vc];
                    float vcj = g_vocab[2][j][vc];
                    float r   = a - bj;
                    float d   = frcp(r);
                    float num = fmaf(sa, vcj, -(ca * vsj));  // 2AA*sin(r)
                    float val = num * d;
                    float alt = fmaf(sa, vsj, ca * vcj);     // 2AA*cos(r) ~ limit
                    acc += (fabsf(r) < GUARD_TH) ? alt : val;
                }
            }
        }
        if (ok) g_C[(size_t)((b * TT + t0 + ttl)) * VV + v] = acc;
    }
}

// ---------------------------------------------------------------------------
// Kernel C: exclusive cumsum over t per (b,v) column; 8-wide load batching
// ---------------------------------------------------------------------------
__global__ void __launch_bounds__(256) cumshift(float* __restrict__ out) {
    int idx = blockIdx.x * blockDim.x + threadIdx.x;
    if (idx >= BB * VV) return;
    int b = idx / VV;
    int v = idx - b * VV;
    const float* crow = g_C + (size_t)b * TT * VV + v;
    float*       orow = out + (size_t)b * TT * VV + v;
    float run = 0.0f;
#pragma unroll 1
    for (int t = 0; t < TT; t += 8) {
        float x[8];
#pragma unroll
        for (int k = 0; k < 8; k++) x[k] = crow[(size_t)(t + k) * VV];
#pragma unroll
        for (int k = 0; k < 8; k++) { orow[(size_t)(t + k) * VV] = run; run += x[k]; }
    }
}

// ---------------------------------------------------------------------------
extern "C" void kernel_launch(void* const* d_in, const int* in_sizes, int n_in,
                              void* d_out, int out_size) {
    const int*   ids   = (const int*)d_in[0];
    const float* freq  = (const float*)d_in[1];
    const float* amp   = (const float*)d_in[2];
    const float* decay = (const float*)d_in[3];
    // d_in[4] = chunk_size: result independent of chunking; ignored.

    build_tables<<<(VV + 255) / 256, 256>>>(freq, amp, decay);

    // 4 per-batch launches (also improves ncu -s5 odds of catching wave_C)
    dim3 gridB((VV + 255) / 256, TT / 16, 1);
    for (int b = 0; b < BB; b++)
        wave_C<<<gridB, 256>>>(ids, b);

    cumshift<<<(BB * VV + 255) / 256, 256>>>((float*)d_out);
}